// round 3
// baseline (speedup 1.0000x reference)
#include <cuda_runtime.h>
#include <math.h>

namespace {
constexpr int B_ = 64, O_ = 64, I_ = 1152, D_ = 16;
constexpr int NCHUNK = 64;  // i-chunks
constexpr int CI = 18;      // I_/NCHUNK
constexpr int BT = 8;       // b per block
constexpr int NBT = 8;      // B_/BT
}
#define EPSF 1e-8f

// ---- scratch (static device arrays; no dynamic allocation allowed) ----
__device__ float g_ai[B_*I_];
__device__ float g_R[B_];
__device__ float g_pm1[NCHUNK*B_*O_*D_];
__device__ float g_pm2[NCHUNK*B_*O_*D_];
__device__ float g_qm1[NCHUNK*B_*O_*D_];
__device__ float g_qm2[NCHUNK*B_*O_*D_];
__device__ float g_qrs[NCHUNK*B_*O_];
__device__ float g_mean0[B_*O_*D_];
__device__ float g_inv2v[B_*O_*D_];
__device__ float g_coef[B_*O_];

// ---- a_i = ||u + EPS|| over last dim ----
__global__ void k_ai(const float* __restrict__ u) {
    int idx = blockIdx.x*256 + threadIdx.x;
    if (idx >= B_*I_) return;
    const float4* up = (const float4*)(u + idx*D_);
    float s = 0.f;
#pragma unroll
    for (int q = 0; q < 4; q++) {
        float4 v = up[q];
        float a = v.x+EPSF, b = v.y+EPSF, c = v.z+EPSF, d = v.w+EPSF;
        s += a*a + b*b + c*c + d*d;
    }
    g_ai[idx] = sqrtf(s);
}

// ---- R[b] = sum_i a_i ----
__global__ void k_Rk() {
    int b = blockIdx.x;
    float s = 0.f;
    for (int i = threadIdx.x; i < I_; i += 128) s += g_ai[b*I_ + i];
#pragma unroll
    for (int k = 16; k >= 1; k >>= 1) s += __shfl_xor_sync(0xffffffffu, s, k);
    __shared__ float ws[4];
    int wid = threadIdx.x >> 5, lane = threadIdx.x & 31;
    if (lane == 0) ws[wid] = s;
    __syncthreads();
    if (threadIdx.x == 0) g_R[b] = ws[0]+ws[1]+ws[2]+ws[3];
}

// ---- Pass A: M1 = sum_i a_i*V, M2 = sum_i a_i*V^2 (chunk partials) ----
// Block: (i-chunk, b-tile). 512 threads; thread owns (o1=t/16, e=t%16) and o2=o1+32.
__global__ void __launch_bounds__(512, 1) k_passA(const float* __restrict__ u,
                                                  const float* __restrict__ W,
                                                  const float* __restrict__ bias) {
    int ic = blockIdx.x >> 3;
    int bt = blockIdx.x & 7;
    int b0 = bt*BT, i0 = ic*CI;
    int t = threadIdx.x;
    int e = t & 15;
    int og = t >> 4;
    int o1 = og, o2 = og + 32;

    __shared__ float u_sh[BT*CI*D_];
    __shared__ float ai_sh[BT*CI];
    for (int k = t; k < BT*CI*D_; k += 512) {
        int bb = k / (CI*D_);
        int r  = k - bb*(CI*D_);
        u_sh[k] = u[((b0+bb)*I_ + i0)*D_ + r];
    }
    for (int k = t; k < BT*CI; k += 512) {
        int bb = k / CI; int ii = k - bb*CI;
        ai_sh[k] = g_ai[(b0+bb)*I_ + i0 + ii];
    }
    __syncthreads();

    float bias1 = bias[o1*D_ + e] + EPSF;
    float bias2 = bias[o2*D_ + e] + EPSF;

    float m1a[BT], m2a[BT], m1b[BT], m2b[BT];
#pragma unroll
    for (int b = 0; b < BT; b++) { m1a[b]=0.f; m2a[b]=0.f; m1b[b]=0.f; m2b[b]=0.f; }

    for (int ii = 0; ii < CI; ii++) {
        int i = i0 + ii;
        const float4* w1p = (const float4*)(W + ((o1*I_ + i)*D_ + e)*D_);
        const float4* w2p = (const float4*)(W + ((o2*I_ + i)*D_ + e)*D_);
        float4 w1[4], w2[4];
#pragma unroll
        for (int q = 0; q < 4; q++) { w1[q] = w1p[q]; w2[q] = w2p[q]; }
#pragma unroll
        for (int b = 0; b < BT; b++) {
            const float* uu = &u_sh[(b*CI + ii)*D_];
            float a = ai_sh[b*CI + ii];
            float v1 = bias1, v2 = bias2;
#pragma unroll
            for (int q = 0; q < 4; q++) {
                float4 uq = *(const float4*)(uu + 4*q);
                v1 += uq.x*w1[q].x + uq.y*w1[q].y + uq.z*w1[q].z + uq.w*w1[q].w;
                v2 += uq.x*w2[q].x + uq.y*w2[q].y + uq.z*w2[q].z + uq.w*w2[q].w;
            }
            m1a[b] += a*v1;  m2a[b] += a*v1*v1;
            m1b[b] += a*v2;  m2b[b] += a*v2*v2;
        }
    }
#pragma unroll
    for (int b = 0; b < BT; b++) {
        int bo1 = (b0+b)*O_ + o1;
        int bo2 = (b0+b)*O_ + o2;
        int base = ic*B_*O_*D_;
        g_pm1[base + bo1*D_ + e] = m1a[b];
        g_pm2[base + bo1*D_ + e] = m2a[b];
        g_pm1[base + bo2*D_ + e] = m1b[b];
        g_pm2[base + bo2*D_ + e] = m2b[b];
    }
}

// ---- Reduce A: mean0, inv2v0, coef0 = a_j0/(p1+EPS) ----
__global__ void k_reduceA(const float* __restrict__ beta_a, const float* __restrict__ beta_u) {
    int bo = blockIdx.x;
    int b = bo >> 6, o = bo & 63;
    int lane = threadIdx.x;
    int e = lane & 15;
    const float* src = (lane < 16) ? g_pm1 : g_pm2;
    float s = 0.f;
#pragma unroll 4
    for (int c = 0; c < NCHUNK; c++) s += src[(c*B_*O_ + bo)*D_ + e];
    float sOther = __shfl_xor_sync(0xffffffffu, s, 16);
    float Rb = g_R[b];
    float rs = Rb * (1.f/64.f);               // rr_sum (rr = 1/64)
    float dinv = 1.f/(rs + EPSF);
    float m1 = s * (1.f/64.f);
    float m2 = sOther * (1.f/64.f);
    float mean = m1 * dinv;
    float var = (m2 - 2.f*mean*m1 + mean*mean*rs)*dinv + 1e-4f;
    float lv = logf(var);
    float Ls = lv, Pv = var;
#pragma unroll
    for (int k = 8; k >= 1; k >>= 1) {
        Ls += __shfl_xor_sync(0xffffffffu, Ls, k);
        Pv *= __shfl_xor_sync(0xffffffffu, Pv, k);
    }
    const float inv_t0 = (float)(0.01*(1.0 - 0.95));
    if (lane < 16) {
        g_mean0[bo*D_ + e] = mean;
        g_inv2v[bo*D_ + e] = 1.f/(2.f*var + EPSF);
        if (e == 0) {
            float cost = rs * (16.f*beta_u[o] + Ls);
            float x = inv_t0 * (beta_a[o] - cost);
            float aj = 1.f/(1.f + expf(-x));
            float p1 = sqrtf(6.2831853071795864f*Pv + EPSF);
            g_coef[bo] = aj / (p1 + EPSF);
        }
    }
}

// ---- Pass B: fused e-step + m-step-1 accumulation (chunk partials) ----
__global__ void __launch_bounds__(512, 1) k_passB(const float* __restrict__ u,
                                                  const float* __restrict__ W,
                                                  const float* __restrict__ bias) {
    extern __shared__ float sm[];
    float* mean_sh = sm;            // 8192
    float* inv_sh  = sm + 8192;     // 8192
    float* coef_sh = sm + 16384;    // 512
    float* ssh     = sm + 16896;    // 512
    float* apsh    = sm + 17408;    // 512
    float* dinv_sh = sm + 17920;    // 16 (padded)
    float* u_sh    = sm + 17936;    // 2304
    float* ai_sh   = sm + 20240;    // 144   total 20384 floats

    int ic = blockIdx.x >> 3;
    int bt = blockIdx.x & 7;
    int b0 = bt*BT, i0 = ic*CI;
    int t = threadIdx.x;
    int e = t & 15;
    int og = t >> 4;
    int o1 = og, o2 = og + 32;
    int wid = t >> 5, lane = t & 31;

    for (int k = t; k < BT*O_*D_; k += 512) {
        mean_sh[k] = g_mean0[b0*O_*D_ + k];
        inv_sh[k]  = g_inv2v[b0*O_*D_ + k];
    }
    for (int k = t; k < BT*O_; k += 512) coef_sh[k] = g_coef[b0*O_ + k];
    for (int k = t; k < BT*CI*D_; k += 512) {
        int bb = k / (CI*D_);
        int r  = k - bb*(CI*D_);
        u_sh[k] = u[((b0+bb)*I_ + i0)*D_ + r];
    }
    for (int k = t; k < BT*CI; k += 512) {
        int bb = k / CI; int ii = k - bb*CI;
        ai_sh[k] = g_ai[(b0+bb)*I_ + i0 + ii];
    }
    __syncthreads();

    float bias1 = bias[o1*D_ + e] + EPSF;
    float bias2 = bias[o2*D_ + e] + EPSF;

    float m1a[BT], m2a[BT], m1b[BT], m2b[BT], r1[BT], r2[BT];
#pragma unroll
    for (int b = 0; b < BT; b++) { m1a[b]=0.f; m2a[b]=0.f; m1b[b]=0.f; m2b[b]=0.f; r1[b]=0.f; r2[b]=0.f; }

    for (int ii = 0; ii < CI; ii++) {
        int i = i0 + ii;
        const float4* w1p = (const float4*)(W + ((o1*I_ + i)*D_ + e)*D_);
        const float4* w2p = (const float4*)(W + ((o2*I_ + i)*D_ + e)*D_);
        float4 w1[4], w2[4];
#pragma unroll
        for (int q = 0; q < 4; q++) { w1[q] = w1p[q]; w2[q] = w2p[q]; }
        float V1[BT], V2[BT];
        // phase 1: votes + Mahalanobis partial sums (reduced over e via butterfly)
#pragma unroll
        for (int b = 0; b < BT; b++) {
            const float* uu = &u_sh[(b*CI + ii)*D_];
            float v1 = bias1, v2 = bias2;
#pragma unroll
            for (int q = 0; q < 4; q++) {
                float4 uq = *(const float4*)(uu + 4*q);
                v1 += uq.x*w1[q].x + uq.y*w1[q].y + uq.z*w1[q].z + uq.w*w1[q].w;
                v2 += uq.x*w2[q].x + uq.y*w2[q].y + uq.z*w2[q].z + uq.w*w2[q].w;
            }
            V1[b] = v1; V2[b] = v2;
            float d1 = v1 - mean_sh[b*1024 + o1*16 + e];
            float d2 = v2 - mean_sh[b*1024 + o2*16 + e];
            float s1 = d1*d1*inv_sh[b*1024 + o1*16 + e];
            float s2 = d2*d2*inv_sh[b*1024 + o2*16 + e];
#pragma unroll
            for (int k = 8; k >= 1; k >>= 1) {
                s1 += __shfl_xor_sync(0xffffffffu, s1, k);
                s2 += __shfl_xor_sync(0xffffffffu, s2, k);
            }
            if (e == 0) { ssh[b*64 + o1] = s1; ssh[b*64 + o2] = s2; }
        }
        __syncthreads();
        // phase 2: deduped exp (one thread per (b,o)) + denominator over o
        if (wid < BT) {
            int b = wid;
            float sA = ssh[b*64 + lane];
            float sB = ssh[b*64 + lane + 32];
            float apA = coef_sh[b*64 + lane]      * __expf(-sA);
            float apB = coef_sh[b*64 + lane + 32] * __expf(-sB);
            apsh[b*64 + lane] = apA;
            apsh[b*64 + lane + 32] = apB;
            float v = apA + apB;
#pragma unroll
            for (int k = 16; k >= 1; k >>= 1) v += __shfl_xor_sync(0xffffffffu, v, k);
            if (lane == 0) dinv_sh[b] = 1.f/(v + EPSF);
        }
        __syncthreads();
        // phase 3: rr and weighted-moment accumulation
#pragma unroll
        for (int b = 0; b < BT; b++) {
            float di = dinv_sh[b];
            float a  = ai_sh[b*CI + ii];
            float rra1 = apsh[b*64 + o1]*di*a;
            float rra2 = apsh[b*64 + o2]*di*a;
            r1[b] += rra1; r2[b] += rra2;
            m1a[b] += rra1*V1[b]; m2a[b] += rra1*V1[b]*V1[b];
            m1b[b] += rra2*V2[b]; m2b[b] += rra2*V2[b]*V2[b];
        }
        __syncthreads();
    }
#pragma unroll
    for (int b = 0; b < BT; b++) {
        int bo1 = (b0+b)*O_ + o1;
        int bo2 = (b0+b)*O_ + o2;
        int base = ic*B_*O_*D_;
        g_qm1[base + bo1*D_ + e] = m1a[b];
        g_qm2[base + bo1*D_ + e] = m2a[b];
        g_qm1[base + bo2*D_ + e] = m1b[b];
        g_qm2[base + bo2*D_ + e] = m2b[b];
        if (e == 0) {
            g_qrs[ic*B_*O_ + bo1] = r1[b];
            g_qrs[ic*B_*O_ + bo2] = r2[b];
        }
    }
}

// ---- Final: reduce pass-B partials, m-step-1 closure, output ----
__global__ void k_final(const float* __restrict__ beta_a, const float* __restrict__ beta_u,
                        float* __restrict__ out) {
    int bo = blockIdx.x;
    int b = bo >> 6, o = bo & 63;
    int lane = threadIdx.x;
    float r = g_qrs[(2*lane)*B_*O_ + bo] + g_qrs[(2*lane+1)*B_*O_ + bo];
#pragma unroll
    for (int k = 16; k >= 1; k >>= 1) r += __shfl_xor_sync(0xffffffffu, r, k);
    float rs = r;
    int e = lane & 15;
    const float* src = (lane < 16) ? g_qm1 : g_qm2;
    float s = 0.f;
#pragma unroll 4
    for (int c = 0; c < NCHUNK; c++) s += src[(c*B_*O_ + bo)*D_ + e];
    float sOther = __shfl_xor_sync(0xffffffffu, s, 16);
    float dinv = 1.f/(rs + EPSF);
    float m1 = s, m2 = sOther;
    float mean = m1*dinv;
    float var = (m2 - 2.f*mean*m1 + mean*mean*rs)*dinv + 1e-4f;
    float lv = logf(var);
    float nm = mean + EPSF;
    float Ls = lv, Ns = nm*nm;
#pragma unroll
    for (int k = 8; k >= 1; k >>= 1) {
        Ls += __shfl_xor_sync(0xffffffffu, Ls, k);
        Ns += __shfl_xor_sync(0xffffffffu, Ns, k);
    }
    const float inv_t1 = (float)(0.01*(1.0 - 0.95*0.95));
    float cost = rs*(16.f*beta_u[o] + Ls);
    float x = inv_t1*(beta_a[o] - cost);
    float aj = 1.f/(1.f + expf(-x));
    float nrm = sqrtf(Ns);
    if (lane < 16) out[bo*D_ + e] = aj*mean/(nrm + EPSF);
}

extern "C" void kernel_launch(void* const* d_in, const int* in_sizes, int n_in,
                              void* d_out, int out_size) {
    const float* u      = (const float*)d_in[0];
    const float* W      = (const float*)d_in[1];
    const float* beta_a = (const float*)d_in[2];
    const float* beta_u = (const float*)d_in[3];
    const float* bias   = (const float*)d_in[4];
    float* out = (float*)d_out;
    constexpr int SMEM_B = 20384*4;
    cudaFuncSetAttribute(k_passB, cudaFuncAttributeMaxDynamicSharedMemorySize, SMEM_B);
    k_ai<<<(B_*I_ + 255)/256, 256>>>(u);
    k_Rk<<<B_, 128>>>();
    k_passA<<<NCHUNK*NBT, 512>>>(u, W, bias);
    k_reduceA<<<B_*O_, 32>>>(beta_a, beta_u);
    k_passB<<<NCHUNK*NBT, 512, SMEM_B>>>(u, W, bias);
    k_final<<<B_*O_, 32>>>(beta_a, beta_u, out);
}

// round 4
// speedup vs baseline: 1.3152x; 1.3152x over previous
#include <cuda_runtime.h>
#include <math.h>

namespace {
constexpr int B_ = 64, O_ = 64, I_ = 1152, D_ = 16;
constexpr int NCHUNK = 36;   // i-chunks
constexpr int CI = 32;       // I_/NCHUNK
constexpr int BT = 8;        // b per block (pass B)
constexpr int NBT = 8;       // B_/BT
constexpr int BTA = 16;      // b per block (pass A)
constexpr int NBTA = 4;      // B_/BTA
}
#define EPSF 1e-8f

typedef unsigned long long ull;

// ---- f32x2 packed-math helpers (FFMA2 only reachable via PTX) ----
__device__ __forceinline__ ull fma2_(ull a, ull b, ull c) {
    ull d; asm("fma.rn.f32x2 %0,%1,%2,%3;" : "=l"(d) : "l"(a), "l"(b), "l"(c)); return d;
}
__device__ __forceinline__ ull mul2_(ull a, ull b) {
    ull d; asm("mul.rn.f32x2 %0,%1,%2;" : "=l"(d) : "l"(a), "l"(b)); return d;
}
__device__ __forceinline__ ull add2_(ull a, ull b) {
    ull d; asm("add.rn.f32x2 %0,%1,%2;" : "=l"(d) : "l"(a), "l"(b)); return d;
}
__device__ __forceinline__ ull pack2(float x, float y) {
    ull r; asm("mov.b64 %0,{%1,%2};" : "=l"(r) : "f"(x), "f"(y)); return r;
}
__device__ __forceinline__ void unpack2(ull v, float& x, float& y) {
    asm("mov.b64 {%0,%1},%2;" : "=f"(x), "=f"(y) : "l"(v));
}

// ---- scratch (static device arrays; no dynamic allocation allowed) ----
__device__ float g_ai[B_*I_];
__device__ float g_R[B_];
__device__ float g_pm1[B_*O_*NCHUNK*D_];   // layout [bo][chunk][e]
__device__ float g_pm2[B_*O_*NCHUNK*D_];
__device__ float g_qm1[B_*O_*NCHUNK*D_];
__device__ float g_qm2[B_*O_*NCHUNK*D_];
__device__ float g_qrs[B_*O_*NCHUNK];      // layout [bo][chunk]
__device__ float2 g_minv[B_*O_*D_];        // (mean0, 1/(2*var0+EPS))
__device__ float g_coef[B_*O_];

// ---- a_i = ||u + EPS|| over last dim ----
__global__ void k_ai(const float* __restrict__ u) {
    int idx = blockIdx.x*256 + threadIdx.x;
    if (idx >= B_*I_) return;
    const float4* up = (const float4*)(u + idx*D_);
    float s = 0.f;
#pragma unroll
    for (int q = 0; q < 4; q++) {
        float4 v = up[q];
        float a = v.x+EPSF, b = v.y+EPSF, c = v.z+EPSF, d = v.w+EPSF;
        s += a*a + b*b + c*c + d*d;
    }
    g_ai[idx] = sqrtf(s);
}

// ---- R[b] = sum_i a_i ----
__global__ void k_Rk() {
    int b = blockIdx.x;
    float s = 0.f;
    for (int i = threadIdx.x; i < I_; i += 128) s += g_ai[b*I_ + i];
#pragma unroll
    for (int k = 16; k >= 1; k >>= 1) s += __shfl_xor_sync(0xffffffffu, s, k);
    __shared__ float ws[4];
    int wid = threadIdx.x >> 5, lane = threadIdx.x & 31;
    if (lane == 0) ws[wid] = s;
    __syncthreads();
    if (threadIdx.x == 0) g_R[b] = ws[0]+ws[1]+ws[2]+ws[3];
}

// ---- Pass A: M1 = sum_i a_i*V, M2 = sum_i a_i*V^2 (chunk partials) ----
// Block = (i-chunk, b-tile of 16). 512 threads; thread owns (o1=t/16, e=t%16), o2=o1+32.
__global__ void __launch_bounds__(512, 1) k_passA(const float* __restrict__ u,
                                                  const float* __restrict__ W,
                                                  const float* __restrict__ bias) {
    int ic = blockIdx.x >> 2;
    int bt = blockIdx.x & 3;
    int b0 = bt*BTA, i0 = ic*CI;
    int t = threadIdx.x;
    int e = t & 15;
    int og = t >> 4;
    int o1 = og, o2 = og + 32;

    __shared__ float u_sh[BTA*CI*D_];   // 8192 floats
    __shared__ float ai_sh[BTA*CI];     // 512
    for (int k = t; k < BTA*CI*D_/4; k += 512) {
        int bb = k >> 7;           // /(CI*D/4)
        int r  = k & 127;
        ((float4*)u_sh)[k] = ((const float4*)(u + ((size_t)(b0+bb)*I_ + i0)*D_))[r];
    }
    for (int k = t; k < BTA*CI; k += 512) {
        int bb = k >> 5; int ii = k & 31;
        ai_sh[k] = g_ai[(b0+bb)*I_ + i0 + ii];
    }
    __syncthreads();

    float bias1 = bias[o1*D_ + e] + EPSF;
    float bias2 = bias[o2*D_ + e] + EPSF;

    ull m1[BTA], m2[BTA];
#pragma unroll
    for (int b = 0; b < BTA; b++) { m1[b] = 0ull; m2[b] = 0ull; }

    for (int ii = 0; ii < CI; ii++) {
        int i = i0 + ii;
        const ulonglong2* w1p = (const ulonglong2*)(W + (((size_t)o1*I_ + i)*D_ + e)*D_);
        const ulonglong2* w2p = (const ulonglong2*)(W + (((size_t)o2*I_ + i)*D_ + e)*D_);
        ulonglong2 w1a = w1p[0], w1b = w1p[1], w1c = w1p[2], w1d = w1p[3];
        ulonglong2 w2a = w2p[0], w2b = w2p[1], w2c = w2p[2], w2d = w2p[3];
#pragma unroll
        for (int b = 0; b < BTA; b++) {
            const ulonglong2* uu = (const ulonglong2*)&u_sh[(b*CI + ii)*D_];
            ulonglong2 u0 = uu[0], u1 = uu[1], u2 = uu[2], u3 = uu[3];
            ull a1 = 0ull, a2 = 0ull;
            a1 = fma2_(u0.x, w1a.x, a1); a2 = fma2_(u0.x, w2a.x, a2);
            a1 = fma2_(u0.y, w1a.y, a1); a2 = fma2_(u0.y, w2a.y, a2);
            a1 = fma2_(u1.x, w1b.x, a1); a2 = fma2_(u1.x, w2b.x, a2);
            a1 = fma2_(u1.y, w1b.y, a1); a2 = fma2_(u1.y, w2b.y, a2);
            a1 = fma2_(u2.x, w1c.x, a1); a2 = fma2_(u2.x, w2c.x, a2);
            a1 = fma2_(u2.y, w1c.y, a1); a2 = fma2_(u2.y, w2c.y, a2);
            a1 = fma2_(u3.x, w1d.x, a1); a2 = fma2_(u3.x, w2d.x, a2);
            a1 = fma2_(u3.y, w1d.y, a1); a2 = fma2_(u3.y, w2d.y, a2);
            float x1, y1, x2, y2;
            unpack2(a1, x1, y1); unpack2(a2, x2, y2);
            float v1 = bias1 + x1 + y1;
            float v2 = bias2 + x2 + y2;
            float a = ai_sh[b*CI + ii];
            ull aa = pack2(a, a);
            ull vv = pack2(v1, v2);
            ull av = mul2_(aa, vv);
            m1[b] = add2_(m1[b], av);
            m2[b] = fma2_(av, vv, m2[b]);
        }
    }
#pragma unroll
    for (int b = 0; b < BTA; b++) {
        int bo1 = (b0+b)*O_ + o1;
        int bo2 = (b0+b)*O_ + o2;
        float m1x, m1y, m2x, m2y;
        unpack2(m1[b], m1x, m1y);
        unpack2(m2[b], m2x, m2y);
        g_pm1[(bo1*NCHUNK + ic)*D_ + e] = m1x;
        g_pm2[(bo1*NCHUNK + ic)*D_ + e] = m2x;
        g_pm1[(bo2*NCHUNK + ic)*D_ + e] = m1y;
        g_pm2[(bo2*NCHUNK + ic)*D_ + e] = m2y;
    }
}

// ---- Reduce A: mean0, inv2v0, coef0 = a_j0/(p1+EPS). 4 bo per block (1 warp each) ----
__global__ void k_reduceA(const float* __restrict__ beta_a, const float* __restrict__ beta_u) {
    int bo = blockIdx.x*4 + (threadIdx.x >> 5);
    int b = bo >> 6, o = bo & 63;
    int lane = threadIdx.x & 31;
    int e = lane & 15;
    const float* src = (lane < 16) ? g_pm1 : g_pm2;
    const float* p = src + bo*(NCHUNK*D_) + e;
    float s = 0.f;
#pragma unroll 4
    for (int c = 0; c < NCHUNK; c++) s += p[c*D_];
    float sOther = __shfl_xor_sync(0xffffffffu, s, 16);
    float Rb = g_R[b];
    float rs = Rb * (1.f/64.f);               // rr_sum (rr = 1/64)
    float dinv = 1.f/(rs + EPSF);
    float m1 = s * (1.f/64.f);
    float m2 = sOther * (1.f/64.f);
    float mean = m1 * dinv;
    float var = (m2 - 2.f*mean*m1 + mean*mean*rs)*dinv + 1e-4f;
    float lv = logf(var);
    float Ls = lv, Pv = var;
#pragma unroll
    for (int k = 8; k >= 1; k >>= 1) {
        Ls += __shfl_xor_sync(0xffffffffu, Ls, k);
        Pv *= __shfl_xor_sync(0xffffffffu, Pv, k);
    }
    const float inv_t0 = (float)(0.01*(1.0 - 0.95));
    if (lane < 16) {
        g_minv[bo*D_ + e] = make_float2(mean, 1.f/(2.f*var + EPSF));
        if (e == 0) {
            float cost = rs * (16.f*beta_u[o] + Ls);
            float x = inv_t0 * (beta_a[o] - cost);
            float aj = 1.f/(1.f + expf(-x));
            float p1 = sqrtf(6.2831853071795864f*Pv + EPSF);
            g_coef[bo] = aj / (p1 + EPSF);
        }
    }
}

// ---- Pass B: fused e-step + m-step-1 accumulation (chunk partials) ----
__global__ void __launch_bounds__(512, 1) k_passB(const float* __restrict__ u,
                                                  const float* __restrict__ W,
                                                  const float* __restrict__ bias) {
    extern __shared__ float sm[];
    float2* minv_sh = (float2*)sm;        // 8192 float2 = 16384 floats
    float* coef_sh = sm + 16384;          // 512
    float* ssh     = sm + 16896;          // 512
    float* apsh    = sm + 17408;          // 512
    float* dinv_sh = sm + 17920;          // 16
    float* u_sh    = sm + 17936;          // 4096
    float* ai_sh   = sm + 22032;          // 256   total 22288 floats

    int ic = blockIdx.x >> 3;
    int bt = blockIdx.x & 7;
    int b0 = bt*BT, i0 = ic*CI;
    int t = threadIdx.x;
    int e = t & 15;
    int og = t >> 4;
    int o1 = og, o2 = og + 32;
    int wid = t >> 5, lane = t & 31;

    for (int k = t; k < BT*O_*D_; k += 512) minv_sh[k] = g_minv[b0*O_*D_ + k];
    for (int k = t; k < BT*O_; k += 512) coef_sh[k] = g_coef[b0*O_ + k];
    for (int k = t; k < BT*CI*D_/4; k += 512) {
        int bb = k >> 7;
        int r  = k & 127;
        ((float4*)u_sh)[k] = ((const float4*)(u + ((size_t)(b0+bb)*I_ + i0)*D_))[r];
    }
    for (int k = t; k < BT*CI; k += 512) {
        int bb = k >> 5; int ii = k & 31;
        ai_sh[k] = g_ai[(b0+bb)*I_ + i0 + ii];
    }
    __syncthreads();

    float bias1 = bias[o1*D_ + e] + EPSF;
    float bias2 = bias[o2*D_ + e] + EPSF;

    ull m1[BT], m2[BT], r[BT], vv[BT];
#pragma unroll
    for (int b = 0; b < BT; b++) { m1[b]=0ull; m2[b]=0ull; r[b]=0ull; }

    for (int ii = 0; ii < CI; ii++) {
        int i = i0 + ii;
        const ulonglong2* w1p = (const ulonglong2*)(W + (((size_t)o1*I_ + i)*D_ + e)*D_);
        const ulonglong2* w2p = (const ulonglong2*)(W + (((size_t)o2*I_ + i)*D_ + e)*D_);
        ulonglong2 w1a = w1p[0], w1b = w1p[1], w1c = w1p[2], w1d = w1p[3];
        ulonglong2 w2a = w2p[0], w2b = w2p[1], w2c = w2p[2], w2d = w2p[3];
        // phase 1: votes + Mahalanobis partial sums (reduced over e via butterfly)
#pragma unroll
        for (int b = 0; b < BT; b++) {
            const ulonglong2* uu = (const ulonglong2*)&u_sh[(b*CI + ii)*D_];
            ulonglong2 u0 = uu[0], u1 = uu[1], u2 = uu[2], u3 = uu[3];
            ull a1 = 0ull, a2 = 0ull;
            a1 = fma2_(u0.x, w1a.x, a1); a2 = fma2_(u0.x, w2a.x, a2);
            a1 = fma2_(u0.y, w1a.y, a1); a2 = fma2_(u0.y, w2a.y, a2);
            a1 = fma2_(u1.x, w1b.x, a1); a2 = fma2_(u1.x, w2b.x, a2);
            a1 = fma2_(u1.y, w1b.y, a1); a2 = fma2_(u1.y, w2b.y, a2);
            a1 = fma2_(u2.x, w1c.x, a1); a2 = fma2_(u2.x, w2c.x, a2);
            a1 = fma2_(u2.y, w1c.y, a1); a2 = fma2_(u2.y, w2c.y, a2);
            a1 = fma2_(u3.x, w1d.x, a1); a2 = fma2_(u3.x, w2d.x, a2);
            a1 = fma2_(u3.y, w1d.y, a1); a2 = fma2_(u3.y, w2d.y, a2);
            float x1, y1, x2, y2;
            unpack2(a1, x1, y1); unpack2(a2, x2, y2);
            float v1 = bias1 + x1 + y1;
            float v2 = bias2 + x2 + y2;
            vv[b] = pack2(v1, v2);
            float2 mi1 = minv_sh[b*1024 + o1*16 + e];
            float2 mi2 = minv_sh[b*1024 + o2*16 + e];
            float d1 = v1 - mi1.x;
            float d2 = v2 - mi2.x;
            float s1 = d1*d1*mi1.y;
            float s2 = d2*d2*mi2.y;
#pragma unroll
            for (int k = 8; k >= 1; k >>= 1) {
                s1 += __shfl_xor_sync(0xffffffffu, s1, k);
                s2 += __shfl_xor_sync(0xffffffffu, s2, k);
            }
            if (e == 0) { ssh[b*64 + o1] = s1; ssh[b*64 + o2] = s2; }
        }
        __syncthreads();
        // phase 2: deduped exp (one thread per (b,o)) + denominator over o
        if (wid < BT) {
            int b = wid;
            float sA = ssh[b*64 + lane];
            float sB = ssh[b*64 + lane + 32];
            float apA = coef_sh[b*64 + lane]      * __expf(-sA);
            float apB = coef_sh[b*64 + lane + 32] * __expf(-sB);
            apsh[b*64 + lane] = apA;
            apsh[b*64 + lane + 32] = apB;
            float v = apA + apB;
#pragma unroll
            for (int k = 16; k >= 1; k >>= 1) v += __shfl_xor_sync(0xffffffffu, v, k);
            if (lane == 0) dinv_sh[b] = 1.f/(v + EPSF);
        }
        __syncthreads();
        // phase 3: rr and weighted-moment accumulation (packed over the o-pair)
#pragma unroll
        for (int b = 0; b < BT; b++) {
            float di = dinv_sh[b];
            float a  = ai_sh[b*CI + ii];
            float da = di*a;
            float rra1 = apsh[b*64 + o1]*da;
            float rra2 = apsh[b*64 + o2]*da;
            ull rp = pack2(rra1, rra2);
            r[b] = add2_(r[b], rp);
            ull rv = mul2_(rp, vv[b]);
            m1[b] = add2_(m1[b], rv);
            m2[b] = fma2_(rv, vv[b], m2[b]);
        }
        __syncthreads();
    }
#pragma unroll
    for (int b = 0; b < BT; b++) {
        int bo1 = (b0+b)*O_ + o1;
        int bo2 = (b0+b)*O_ + o2;
        float m1x, m1y, m2x, m2y, rx, ry;
        unpack2(m1[b], m1x, m1y);
        unpack2(m2[b], m2x, m2y);
        unpack2(r[b], rx, ry);
        g_qm1[(bo1*NCHUNK + ic)*D_ + e] = m1x;
        g_qm2[(bo1*NCHUNK + ic)*D_ + e] = m2x;
        g_qm1[(bo2*NCHUNK + ic)*D_ + e] = m1y;
        g_qm2[(bo2*NCHUNK + ic)*D_ + e] = m2y;
        if (e == 0) {
            g_qrs[bo1*NCHUNK + ic] = rx;
            g_qrs[bo2*NCHUNK + ic] = ry;
        }
    }
}

// ---- Final: reduce pass-B partials, m-step-1 closure, output. 4 bo per block ----
__global__ void k_final(const float* __restrict__ beta_a, const float* __restrict__ beta_u,
                        float* __restrict__ out) {
    int bo = blockIdx.x*4 + (threadIdx.x >> 5);
    int o = bo & 63;
    int lane = threadIdx.x & 31;
    float rr = 0.f;
    for (int c = lane; c < NCHUNK; c += 32) rr += g_qrs[bo*NCHUNK + c];
#pragma unroll
    for (int k = 16; k >= 1; k >>= 1) rr += __shfl_xor_sync(0xffffffffu, rr, k);
    float rs = rr;
    int e = lane & 15;
    const float* src = (lane < 16) ? g_qm1 : g_qm2;
    const float* p = src + bo*(NCHUNK*D_) + e;
    float s = 0.f;
#pragma unroll 4
    for (int c = 0; c < NCHUNK; c++) s += p[c*D_];
    float sOther = __shfl_xor_sync(0xffffffffu, s, 16);
    float dinv = 1.f/(rs + EPSF);
    float m1 = s, m2 = sOther;
    float mean = m1*dinv;
    float var = (m2 - 2.f*mean*m1 + mean*mean*rs)*dinv + 1e-4f;
    float lv = logf(var);
    float nm = mean + EPSF;
    float Ls = lv, Ns = nm*nm;
#pragma unroll
    for (int k = 8; k >= 1; k >>= 1) {
        Ls += __shfl_xor_sync(0xffffffffu, Ls, k);
        Ns += __shfl_xor_sync(0xffffffffu, Ns, k);
    }
    const float inv_t1 = (float)(0.01*(1.0 - 0.95*0.95));
    float cost = rs*(16.f*beta_u[o] + Ls);
    float x = inv_t1*(beta_a[o] - cost);
    float aj = 1.f/(1.f + expf(-x));
    float nrm = sqrtf(Ns);
    if (lane < 16) out[bo*D_ + e] = aj*mean/(nrm + EPSF);
}

extern "C" void kernel_launch(void* const* d_in, const int* in_sizes, int n_in,
                              void* d_out, int out_size) {
    const float* u      = (const float*)d_in[0];
    const float* W      = (const float*)d_in[1];
    const float* beta_a = (const float*)d_in[2];
    const float* beta_u = (const float*)d_in[3];
    const float* bias   = (const float*)d_in[4];
    float* out = (float*)d_out;
    constexpr int SMEM_B = 22288*4;
    cudaFuncSetAttribute(k_passB, cudaFuncAttributeMaxDynamicSharedMemorySize, SMEM_B);
    k_ai<<<(B_*I_ + 255)/256, 256>>>(u);
    k_Rk<<<B_, 128>>>();
    k_passA<<<NCHUNK*NBTA, 512>>>(u, W, bias);
    k_reduceA<<<B_*O_/4, 128>>>(beta_a, beta_u);
    k_passB<<<NCHUNK*NBT, 512, SMEM_B>>>(u, W, bias);
    k_final<<<B_*O_/4, 128>>>(beta_a, beta_u, out);
}